// round 5
// baseline (speedup 1.0000x reference)
#include <cuda_runtime.h>

// Problem constants (shapes fixed by the dataset)
#define NB   16
#define C    256
#define HW   16384          // 128*128
#define CLS  9
#define P    (NB*HW)        // 262144 pixels
#define NT   256
#define NBLK_ARG ((P/2)/NT) // 512 argmax blocks (2 pixels/thread)
#define CHG  8              // channels per accum block
#define HALFPX 8192         // pixels per half-plane
#define NACC (NB*(C/CHG)*2) // 1024 accum blocks  (one full wave)

// Scratch (no allocation; every word fully overwritten each replay)
__device__ unsigned char g_labels[P];
__device__ int           g_cnt_part[NBLK_ARG * CLS];
__device__ float         g_part[NB * C * 2 * CLS];   // per (n,ch,half)

// ---------------------------------------------------------------------------
// 1) per-pixel argmax (float2, 2 px/thread) -> labels + per-block counts
// ---------------------------------------------------------------------------
__global__ void __launch_bounds__(NT) argmax_kernel(const float* __restrict__ logit) {
    __shared__ int s_cnt[CLS];
    const int tid = threadIdx.x;
    if (tid < CLS) s_cnt[tid] = 0;
    __syncthreads();

    const int g   = blockIdx.x * NT + tid;   // float2-group index
    const int n   = g >> 13;                 // g / (HW/2)
    const int hw2 = g & 8191;

    const float2* lp = (const float2*)logit;
    float2 best = lp[(size_t)(n*CLS + 0) * (HW/2) + hw2];
    int lx = 0, ly = 0;
    #pragma unroll
    for (int cls = 1; cls < CLS; cls++) {
        float2 v = lp[(size_t)(n*CLS + cls) * (HW/2) + hw2];
        if (v.x > best.x) { best.x = v.x; lx = cls; }
        if (v.y > best.y) { best.y = v.y; ly = cls; }
    }
    g_labels[2*g]   = (unsigned char)lx;
    g_labels[2*g+1] = (unsigned char)ly;

    atomicAdd(&s_cnt[lx], 1);
    atomicAdd(&s_cnt[ly], 1);
    __syncthreads();
    if (tid < CLS) g_cnt_part[blockIdx.x * CLS + tid] = s_cnt[tid];
}

// ---------------------------------------------------------------------------
// 2) accumulate: block = (n, 8-channel group, half-plane). Labels staged
//    once into SMEM (kills the 64 MiB label L2 re-read), then 8 channels
//    streamed through the bank-conflict-free acc[cls][tid] scatter with a
//    per-channel shfl-butterfly reduce. Grid = 1024 = one full wave.
// ---------------------------------------------------------------------------
__global__ void __launch_bounds__(NT) accum_kernel(const float* __restrict__ feat) {
    __shared__ float        acc[CLS * NT];
    __shared__ float        s_warp[CLS * 8];
    __shared__ unsigned int s_lab[HALFPX / 4];       // 8192 labels = 2048 words
    const int tid = threadIdx.x;

    const int b    = blockIdx.x;          // 0..1023
    const int n    = b >> 6;              // 64 blocks per image
    const int rem  = b & 63;
    const int grp  = rem >> 1;            // channel group 0..31
    const int half = rem & 1;

    // stage labels for this (n, half) into SMEM
    const unsigned int* glab =
        (const unsigned int*)(g_labels + (size_t)n * HW + half * HALFPX);
    #pragma unroll
    for (int k = 0; k < (HALFPX/4)/NT; k++)   // 8 iters
        s_lab[tid + k*NT] = glab[tid + k*NT];

    #pragma unroll
    for (int l = 0; l < CLS; l++) acc[l*NT + tid] = 0.0f;
    __syncthreads();

    const int warp = tid >> 5, lane = tid & 31;

    #pragma unroll
    for (int j = 0; j < CHG; j++) {
        const int ch = grp*CHG + j;
        const float4* fp = (const float4*)feat
                         + (size_t)(n*C + ch) * (HW/4) + half * (HALFPX/4);

        #pragma unroll
        for (int k = 0; k < (HALFPX/4)/NT; k++) {   // 8 iters
            const int i = tid + k*NT;
            float4 v = fp[i];
            uchar4 l = ((const uchar4*)s_lab)[i];
            acc[l.x*NT + tid] += v.x;
            acc[l.y*NT + tid] += v.y;
            acc[l.z*NT + tid] += v.z;
            acc[l.w*NT + tid] += v.w;
        }
        __syncthreads();

        // butterfly reduce the 9 class sums; zero acc for next channel
        float s[CLS];
        #pragma unroll
        for (int c = 0; c < CLS; c++) {
            s[c] = acc[c*NT + tid];
            acc[c*NT + tid] = 0.0f;
        }
        #pragma unroll
        for (int off = 16; off > 0; off >>= 1) {
            #pragma unroll
            for (int c = 0; c < CLS; c++)
                s[c] += __shfl_xor_sync(0xFFFFFFFFu, s[c], off);
        }
        if (lane == 0) {
            #pragma unroll
            for (int c = 0; c < CLS; c++) s_warp[c*8 + warp] = s[c];
        }
        __syncthreads();

        if (tid < CLS) {
            float t = 0.0f;
            #pragma unroll
            for (int w = 0; w < 8; w++) t += s_warp[tid*8 + w];
            g_part[((size_t)(n*C + ch)*2 + half)*CLS + tid] = t;
        }
        // no extra sync needed: next channel's writes to acc only conflict
        // after the __syncthreads() inside the next iteration's reduce path;
        // but acc zeroing above races with s_warp read? No: s_warp read is
        // after the sync, and acc zero happens before butterfly - safe via
        // the __syncthreads() above. Next channel RMWs acc only after it,
        // and all threads passed it. OK.
    }
}

// ---------------------------------------------------------------------------
// 3) finalize: 9 blocks x 256 threads. Each thread owns one (ch,cls) pair:
//    sum 32 L2-resident partials, scale by 1/count, broadcast over batch.
// ---------------------------------------------------------------------------
__global__ void __launch_bounds__(NT) out_kernel(float* __restrict__ out) {
    __shared__ float s_wcnt[CLS * 8];
    __shared__ float s_inv[CLS];
    const int tid = threadIdx.x;

    // counts: thread t sums argmax blocks t and t+256
    float c[CLS];
    #pragma unroll
    for (int l = 0; l < CLS; l++)
        c[l] = (float)g_cnt_part[tid*CLS + l]
             + (float)g_cnt_part[(tid + NT)*CLS + l];
    #pragma unroll
    for (int off = 16; off > 0; off >>= 1) {
        #pragma unroll
        for (int l = 0; l < CLS; l++)
            c[l] += __shfl_xor_sync(0xFFFFFFFFu, c[l], off);
    }
    const int warp = tid >> 5, lane = tid & 31;
    if (lane == 0) {
        #pragma unroll
        for (int l = 0; l < CLS; l++) s_wcnt[l*8 + warp] = c[l];
    }
    __syncthreads();
    if (tid < CLS) {
        float s = 0.0f;
        #pragma unroll
        for (int w = 0; w < 8; w++) s += s_wcnt[tid*8 + w];
        s_inv[tid] = 1.0f / fmaxf(s, 1.0f);
    }
    __syncthreads();

    const int idx = blockIdx.x * NT + tid;   // 0..2303 (C*CLS)
    if (idx >= C*CLS) return;
    const int ch  = idx / CLS;
    const int cls = idx - ch*CLS;

    float s = 0.0f;
    #pragma unroll
    for (int n = 0; n < NB; n++) {
        const size_t base = ((size_t)(n*C + ch)*2)*CLS + cls;
        s += g_part[base] + g_part[base + CLS];
    }
    const float val = s * s_inv[cls];
    #pragma unroll
    for (int n = 0; n < NB; n++)
        out[n*(C*CLS) + idx] = val;
}

// ---------------------------------------------------------------------------
extern "C" void kernel_launch(void* const* d_in, const int* in_sizes, int n_in,
                              void* d_out, int out_size) {
    const float* feat  = (const float*)d_in[0];
    const float* logit = (const float*)d_in[1];
    float* out = (float*)d_out;

    argmax_kernel<<<NBLK_ARG, NT>>>(logit);          // 512 blocks
    accum_kernel<<<NACC, NT>>>(feat);                // 1024 blocks, one wave
    out_kernel<<<(C*CLS + NT - 1)/NT, NT>>>(out);    // 9 blocks
}

// round 7
// speedup vs baseline: 1.0287x; 1.0287x over previous
#include <cuda_runtime.h>

// Problem constants (shapes fixed by the dataset)
#define NB    16
#define C     256
#define HW    16384         // 128*128
#define CLS   9
#define P     (NB*HW)       // 262144 pixels
#define NT    256
#define GRID  1024          // one wave (needs 7 blocks/SM resident; 148*7=1036)
#define NPLANE (NB*C)       // 4096 planes, = GRID*4 exactly

// Scratch (no allocation). g_barrier is monotonic across graph replays:
// each kernel execution consumes exactly 2*GRID tickets, so the
// (old/GRID + 1)*GRID target formula stays aligned forever.
__device__ unsigned char g_labels[P];
__device__ int           g_cnt_part[GRID * CLS];
__device__ float         g_part[NPLANE * CLS];
__device__ unsigned int  g_barrier;     // zero-initialized at module load

__device__ __forceinline__ unsigned bar_arrive() {
    __threadfence();                                    // release
    return atomicAdd(&g_barrier, 1u);
}
__device__ __forceinline__ void bar_wait(unsigned old) {
    const unsigned target = (old / GRID + 1u) * GRID;
    const volatile unsigned* p = (const volatile unsigned*)&g_barrier;
    while (*p < target) { }
    __threadfence();                                    // acquire
}

__global__ void __launch_bounds__(NT, 7) fused_kernel(
        const float* __restrict__ feat,
        const float* __restrict__ logit,
        float* __restrict__ out) {
    __shared__ float    acc[CLS * NT];
    __shared__ float    s_warp[CLS * 8];
    __shared__ int      s_cnt[CLS];
    __shared__ unsigned s_ticket;

    const int tid  = threadIdx.x;
    const int bid  = blockIdx.x;
    const int warp = tid >> 5, lane = tid & 31;

    // ======================= Phase 1: argmax =======================
    if (tid < CLS) s_cnt[tid] = 0;
    __syncthreads();

    {
        const int p  = bid * NT + tid;      // exactly 1 pixel per thread
        const int n  = p >> 14;             // p / HW
        const int hw = p & 16383;

        const float* lp = logit + (size_t)n * CLS * HW + hw;
        float best = lp[0];
        int   lab  = 0;
        #pragma unroll
        for (int cls = 1; cls < CLS; cls++) {
            float v = lp[(size_t)cls * HW];
            if (v > best) { best = v; lab = cls; }
        }
        g_labels[p] = (unsigned char)lab;
        atomicAdd(&s_cnt[lab], 1);
    }
    __syncthreads();
    if (tid < CLS) g_cnt_part[bid * CLS + tid] = s_cnt[tid];
    __syncthreads();

    // ---- grid barrier 1: all labels visible before accumulation ----
    if (tid == 0) {
        unsigned old = bar_arrive();
        bar_wait(old);
        s_ticket = 0;   // unused slot write keeps s_ticket live
    }
    __syncthreads();

    // ======================= Phase 2: accumulate ====================
    // 4 planes per block, R1-proven inner loop.
    #pragma unroll
    for (int rep = 0; rep < NPLANE/GRID; rep++) {       // 4 planes
        const int nc = bid + rep * GRID;                // plane index
        const int n  = nc >> 8;                         // nc / C

        #pragma unroll
        for (int l = 0; l < CLS; l++) acc[l*NT + tid] = 0.0f;
        __syncthreads();

        const float4* fp = (const float4*)feat     + (size_t)nc * (HW/4);
        const uchar4* lp = (const uchar4*)g_labels + (size_t)n  * (HW/4);

        #pragma unroll
        for (int k = 0; k < (HW/4)/NT; k++) {           // 16 iterations
            const int i = tid + k*NT;
            float4 v = fp[i];
            uchar4 l = lp[i];
            acc[l.x*NT + tid] += v.x;
            acc[l.y*NT + tid] += v.y;
            acc[l.z*NT + tid] += v.z;
            acc[l.w*NT + tid] += v.w;
        }
        __syncthreads();

        // butterfly reduce all 9 classes
        float s[CLS];
        #pragma unroll
        for (int c = 0; c < CLS; c++) s[c] = acc[c*NT + tid];
        #pragma unroll
        for (int off = 16; off > 0; off >>= 1) {
            #pragma unroll
            for (int c = 0; c < CLS; c++)
                s[c] += __shfl_xor_sync(0xFFFFFFFFu, s[c], off);
        }
        if (lane == 0) {
            #pragma unroll
            for (int c = 0; c < CLS; c++) s_warp[c*8 + warp] = s[c];
        }
        __syncthreads();

        if (tid < CLS) {
            float t = 0.0f;
            #pragma unroll
            for (int w = 0; w < 8; w++) t += s_warp[tid*8 + w];
            g_part[nc*CLS + tid] = t;
        }
        __syncthreads();
    }

    // ---- grid barrier 2: partials visible; only blocks 0..8 spin ----
    if (tid == 0) s_ticket = bar_arrive();
    __syncthreads();
    if (bid >= CLS) return;                 // 1015 blocks exit, no spin
    if (tid == 0) bar_wait(s_ticket);
    __syncthreads();

    // ======================= Phase 3: finalize ======================
    __shared__ float s_wcnt[CLS * 8];
    __shared__ float s_inv[CLS];

    // counts: thread t sums blocks t, t+256, t+512, t+768
    float c[CLS];
    #pragma unroll
    for (int l = 0; l < CLS; l++) c[l] = 0.0f;
    #pragma unroll
    for (int r = 0; r < GRID/NT; r++) {
        #pragma unroll
        for (int l = 0; l < CLS; l++)
            c[l] += (float)g_cnt_part[(r*NT + tid)*CLS + l];
    }
    #pragma unroll
    for (int off = 16; off > 0; off >>= 1) {
        #pragma unroll
        for (int l = 0; l < CLS; l++)
            c[l] += __shfl_xor_sync(0xFFFFFFFFu, c[l], off);
    }
    if (lane == 0) {
        #pragma unroll
        for (int l = 0; l < CLS; l++) s_wcnt[l*8 + warp] = c[l];
    }
    __syncthreads();
    if (tid < CLS) {
        float s = 0.0f;
        #pragma unroll
        for (int w = 0; w < 8; w++) s += s_wcnt[tid*8 + w];
        s_inv[tid] = 1.0f / fmaxf(s, 1.0f);
    }
    __syncthreads();

    const int idx = bid * NT + tid;         // 0..2303 = C*CLS
    const int ch  = idx / CLS;
    const int cls = idx - ch*CLS;

    float s = 0.0f;
    #pragma unroll
    for (int n = 0; n < NB; n++)
        s += g_part[(n*C + ch)*CLS + cls];
    const float val = s * s_inv[cls];
    #pragma unroll
    for (int n = 0; n < NB; n++)
        out[n*(C*CLS) + idx] = val;
}

// ---------------------------------------------------------------------------
extern "C" void kernel_launch(void* const* d_in, const int* in_sizes, int n_in,
                              void* d_out, int out_size) {
    const float* feat  = (const float*)d_in[0];
    const float* logit = (const float*)d_in[1];
    float* out = (float*)d_out;

    fused_kernel<<<GRID, NT>>>(feat, logit, out);   // one launch, one wave
}